// round 14
// baseline (speedup 1.0000x reference)
#include <cuda_runtime.h>
#include <cuda_fp16.h>
#include <cstdint>

// Problem constants
#define NN    8192
#define F_IN  512
#define F_OUT 256
#define ALPHA 0.2f
#define NEG_INF (-9e15f)
#define FLT_MAXN 3.402823466e38f

// -------- scratch (device globals: no allocations allowed) ----------------
__device__ float   g_h [NN * F_OUT];   // h = x @ W (fp32, for f1/f2)
__device__ float   g_ht[NN * F_OUT];   // h tf32-rounded, ROW major (mma B src)
__device__ float   g_f1[NN];
__device__ float   g_f2[NN];
__device__ __align__(16) float2 g_e2[NN];   // (exp(f2_j), exp(0.2*f2_j))
__device__ float4  g_rc[NN];           // per-row (A, C, Bthr, 1/l)
__device__ uint8_t g_bits[NN * (NN / 8)];  // packed adj>0 bits (8 MB)

__device__ __forceinline__ float to_tf32(float x) {
    uint32_t r;
    asm("cvt.rna.tf32.f32 %0, %1;" : "=r"(r) : "f"(x));
    return __uint_as_float(r);
}

__device__ __forceinline__ uint32_t smem_u32(const void* p) {
    uint32_t a;
    asm("{ .reg .u64 t; cvta.to.shared.u64 t, %1; cvt.u32.u64 %0, t; }"
        : "=r"(a) : "l"(p));
    return a;
}

__device__ __forceinline__ void ldsm4(uint32_t& r0, uint32_t& r1,
                                      uint32_t& r2, uint32_t& r3, uint32_t addr) {
    asm volatile("ldmatrix.sync.aligned.m8n8.x4.shared.b16 {%0,%1,%2,%3}, [%4];"
                 : "=r"(r0), "=r"(r1), "=r"(r2), "=r"(r3) : "r"(addr));
}

// ===========================================================================
// Kernel 1: h = x @ W  (8192x512 @ 512x256); fp32 h + tf32-rounded row-major
// ===========================================================================
__global__ __launch_bounds__(256) void gemm1_kernel(
    const float* __restrict__ X, const float* __restrict__ W)
{
    __shared__ float Xs[16][64];
    __shared__ float Ws[16][64];

    const int t   = threadIdx.x;
    const int tx  = t & 15;
    const int ty  = t >> 4;
    const int row0 = blockIdx.x * 64;
    const int col0 = blockIdx.y * 64;

    float acc[4][4];
#pragma unroll
    for (int i = 0; i < 4; ++i)
#pragma unroll
        for (int j = 0; j < 4; ++j) acc[i][j] = 0.f;

    for (int k0 = 0; k0 < F_IN; k0 += 16) {
        {
            int r  = t >> 2;
            int kq = (t & 3) * 4;
            float4 v = *(const float4*)&X[(size_t)(row0 + r) * F_IN + k0 + kq];
            Xs[kq + 0][r] = v.x;
            Xs[kq + 1][r] = v.y;
            Xs[kq + 2][r] = v.z;
            Xs[kq + 3][r] = v.w;
        }
        {
            int kr = t >> 4;
            int cq = (t & 15) * 4;
            *(float4*)&Ws[kr][cq] =
                *(const float4*)&W[(size_t)(k0 + kr) * F_OUT + col0 + cq];
        }
        __syncthreads();

#pragma unroll
        for (int kk = 0; kk < 16; ++kk) {
            float a4[4], b4[4];
            *(float4*)a4 = *(const float4*)&Xs[kk][ty * 4];
            *(float4*)b4 = *(const float4*)&Ws[kk][tx * 4];
#pragma unroll
            for (int i = 0; i < 4; ++i)
#pragma unroll
                for (int j = 0; j < 4; ++j)
                    acc[i][j] = fmaf(a4[i], b4[j], acc[i][j]);
        }
        __syncthreads();
    }

#pragma unroll
    for (int i = 0; i < 4; ++i) {
        size_t off = (size_t)(row0 + ty * 4 + i) * F_OUT + col0 + tx * 4;
        *(float4*)&g_h[off]  = make_float4(acc[i][0], acc[i][1], acc[i][2], acc[i][3]);
        *(float4*)&g_ht[off] = make_float4(to_tf32(acc[i][0]), to_tf32(acc[i][1]),
                                           to_tf32(acc[i][2]), to_tf32(acc[i][3]));
    }
}

// ===========================================================================
// Kernel 2: f1 / f2 row dot products + e2 table
// ===========================================================================
__global__ __launch_bounds__(256) void f12_kernel(const float* __restrict__ a)
{
    const int warp = threadIdx.x >> 5;
    const int lane = threadIdx.x & 31;
    const int row  = blockIdx.x * 8 + warp;
    if (row >= NN) return;

    const float* hr = &g_h[(size_t)row * F_OUT];
    float s1 = 0.f, s2 = 0.f;
#pragma unroll
    for (int q = 0; q < 8; ++q) {
        int f = lane + q * 32;
        float v = hr[f];
        s1 = fmaf(v, a[f], s1);
        s2 = fmaf(v, a[F_OUT + f], s2);
    }
#pragma unroll
    for (int off = 16; off > 0; off >>= 1) {
        s1 += __shfl_xor_sync(0xffffffffu, s1, off);
        s2 += __shfl_xor_sync(0xffffffffu, s2, off);
    }
    if (lane == 0) {
        g_f1[row] = s1;
        g_f2[row] = s2;
        g_e2[row] = make_float2(__expf(s2), __expf(ALPHA * s2));
    }
}

// ===========================================================================
// Kernel 3: rowstats — streams adj + f2. Online (m, l) stats, emits
// rc = (A, C, Bthr, 1/l) and the packed adjacency bits.
// ===========================================================================
__global__ __launch_bounds__(256) void rowstats_kernel(const int* __restrict__ adj)
{
    const int warp = threadIdx.x >> 5;
    const int lane = threadIdx.x & 31;
    const int row  = blockIdx.x * 8 + warp;

    const int* arow = adj + (size_t)row * NN;
    uint8_t* brow   = g_bits + (size_t)row * (NN / 8);
    const float f1v = g_f1[row];

    float m = -FLT_MAXN;
    float l = 0.f;

    for (int j0 = lane * 8; j0 < NN; j0 += 256) {
        int4   A0 = *(const int4*)&arow[j0];
        int4   A1 = *(const int4*)&arow[j0 + 4];
        float4 F0 = *(const float4*)&g_f2[j0];
        float4 F1 = *(const float4*)&g_f2[j0 + 4];

        int   av[8] = {A0.x, A0.y, A0.z, A0.w, A1.x, A1.y, A1.z, A1.w};
        float fv[8] = {F0.x, F0.y, F0.z, F0.w, F1.x, F1.y, F1.z, F1.w};
        float sv[8];
        uint32_t bits = 0;
#pragma unroll
        for (int k = 0; k < 8; ++k) {
            float e = f1v + fv[k];
            e = (e > 0.f) ? e : ALPHA * e;
            bool msk = av[k] > 0;
            sv[k] = msk ? e : NEG_INF;
            bits |= (msk ? 1u : 0u) << k;
        }
        brow[j0 >> 3] = (uint8_t)bits;

        float cm = sv[0];
#pragma unroll
        for (int k = 1; k < 8; ++k) cm = fmaxf(cm, sv[k]);
        float mn = fmaxf(m, cm);
        float s = 0.f;
#pragma unroll
        for (int k = 0; k < 8; ++k) s += __expf(sv[k] - mn);
        l = l * __expf(m - mn) + s;
        m = mn;
    }

#pragma unroll
    for (int off = 16; off > 0; off >>= 1) {
        float m2 = __shfl_xor_sync(0xffffffffu, m, off);
        float l2 = __shfl_xor_sync(0xffffffffu, l, off);
        float mn = fmaxf(m, m2);
        l = l * __expf(m - mn) + l2 * __expf(m2 - mn);
        m = mn;
    }
    if (lane == 0) {
        float A = 0.f, C = 0.f, il = 0.f;
        if (l > 0.f) {
            A  = __expf(f1v - m);
            C  = __expf(ALPHA * f1v - m);
            il = 1.f / l;
        }
        g_rc[row] = make_float4(A, C, __expf(-f1v), il);
    }
}

// ===========================================================================
// Kernel 4: att @ h via tf32 mma m16n8k8.
// Grid (128, 2): x = 64-row block, y = 128-col half of F_OUT. 256 threads,
// 2 CTAs/SM (latency cover). j-tile 64 -> 128 tiles, half the barriers.
// Double-buffered cp.async h; p built exp-free from bits, stored directly
// into the opposite buffer after the head barrier (race-free: that buffer's
// last readers finished before the previous tail barrier).
// ===========================================================================
#define BM2    64
#define BN2    64
#define NC2    128                  // cols per CTA
#define NT     (NN / BN2)           // 128 tiles
#define PS     68                   // p_s row stride (floats), 68%32=4
#define HS     136                  // h_s row stride (floats), 136%32=8
#define HBUF_F (BN2 * HS)           // 8704 floats per h buffer
#define PBUF_F (BM2 * PS)           // 4352 floats per p buffer
#define SMEM_BYTES ((2 * HBUF_F + 2 * PBUF_F) * 4)   // 104448 B

__global__ __launch_bounds__(256, 2) void gat_mma_kernel(float* __restrict__ out)
{
    extern __shared__ float smemf[];
    float* h_s = smemf;                  // [2][BN2][HS]  ([k][n]) n = local col
    float* p_s = smemf + 2 * HBUF_F;     // [2][BM2][PS]  ([m][k])
    const uint32_t h_a = smem_u32(h_s);
    const uint32_t p_a = smem_u32(p_s);

    const int t    = threadIdx.x;
    const int warp = t >> 5;
    const int lane = t & 31;
    const int rowbase = blockIdx.x * BM2;
    const int colbase = blockIdx.y * NC2;

    // mma mapping: warp (w&1) -> 32-row half, (w>>1) -> 32 local cols
    const int mrow  = (warp & 1) * 32;
    const int ncolL = (warp >> 1) * 32;
    const int gr    = lane >> 2;
    const int tg    = lane & 3;

    // ldmatrix lane offsets for A (p_s [m][k], tf32-as-b16 trick)
    const int lrow = lane & 7;
    const int lp8  = (lane >> 3) & 1;
    const int lc4  = (lane >> 4) & 1;
    int aoff[2];
#pragma unroll
    for (int mt = 0; mt < 2; ++mt)
        aoff[mt] = (mrow + mt * 16 + lp8 * 8 + lrow) * PS + lc4 * 4;

    // p-build mapping: thread -> row pr (0..63), 16 j at pj
    const int pr = t >> 2;
    const int pj = (t & 3) * 16;
    const float4 rc = g_rc[rowbase + pr];      // (A, C, Bthr, il)
    const uint8_t* brow = g_bits + (size_t)(rowbase + pr) * (NN / 8);

    float c[2][4][4];                // [m-tile][n-tile][frag]
#pragma unroll
    for (int mt = 0; mt < 2; ++mt)
#pragma unroll
        for (int nt = 0; nt < 4; ++nt)
#pragma unroll
            for (int q = 0; q < 4; ++q) c[mt][nt][q] = 0.f;

    // p-build into given buffer for tile starting at jn
    auto build_p = [&](int bufIdx, int jn) {
        uint32_t w = *(const uint16_t*)&brow[(jn + pj) >> 3];
        float* pd = &p_s[bufIdx * PBUF_F + pr * PS + pj];
#pragma unroll
        for (int q = 0; q < 4; ++q) {
            float4 E0 = *(const float4*)&g_e2[jn + pj + q * 4];
            float4 E1 = *(const float4*)&g_e2[jn + pj + q * 4 + 2];
            float bv[4] = {E0.x, E0.z, E1.x, E1.z};
            float dv[4] = {E0.y, E0.w, E1.y, E1.w};
            float pv[4];
#pragma unroll
            for (int k = 0; k < 4; ++k) {
                bool msk = (w >> (q * 4 + k)) & 1u;
                bool cond = bv[k] > rc.z;
                float p = (cond ? bv[k] : dv[k]) * (cond ? rc.x : rc.y);
                pv[k] = to_tf32(msk ? p : 0.f);
            }
            *(float4*)&pd[q * 4] = make_float4(pv[0], pv[1], pv[2], pv[3]);
        }
    };

    // cp.async the h tile for rows [jn, jn+64), cols [colbase, colbase+128)
    auto load_h = [&](int bufIdx, int jn) {
#pragma unroll
        for (int q = 0; q < 8; ++q) {
            int fi = q * 256 + t;            // float4 idx 0..2047
            int jj = fi >> 5;                // 32 float4 per row
            int ff = (fi & 31) * 4;
            uint32_t dst = h_a + (uint32_t)(bufIdx * HBUF_F + jj * HS + ff) * 4;
            const float* src = &g_ht[(size_t)(jn + jj) * F_OUT + colbase + ff];
            asm volatile("cp.async.cg.shared.global [%0], [%1], 16;\n"
                         :: "r"(dst), "l"(src));
        }
        asm volatile("cp.async.commit_group;\n" ::: "memory");
    };

    // ---------------- prologue: tile 0 ---------------------------------
    build_p(0, 0);
    load_h(0, 0);

    // ---------------- main loop ----------------------------------------
    for (int it = 0; it < NT; ++it) {
        const int buf = it & 1;
        const bool more = (it + 1 < NT);

        if (more) load_h(buf ^ 1, (it + 1) * BN2);

        if (more) asm volatile("cp.async.wait_group 1;\n" ::: "memory");
        else      asm volatile("cp.async.wait_group 0;\n" ::: "memory");
        __syncthreads();   // head: h(it) + p(it) visible to all

        // ---- tensor-core GEMM on this tile (8 k-steps) -----------------
        const float* hb = &h_s[buf * HBUF_F];
        const uint32_t pbase = p_a + (uint32_t)(buf * PBUF_F) * 4;
#pragma unroll
        for (int ks = 0; ks < 8; ++ks) {
            int kb = ks * 8;
            uint32_t Af[2][4];
            ldsm4(Af[0][0], Af[0][1], Af[0][2], Af[0][3],
                  pbase + (uint32_t)(aoff[0] + kb) * 4);
            ldsm4(Af[1][0], Af[1][1], Af[1][2], Af[1][3],
                  pbase + (uint32_t)(aoff[1] + kb) * 4);
#pragma unroll
            for (int nt = 0; nt < 4; ++nt) {
                int n0 = ncolL + nt * 8 + gr;
                uint32_t b0 = __float_as_uint(hb[(kb + tg)     * HS + n0]);
                uint32_t b1 = __float_as_uint(hb[(kb + tg + 4) * HS + n0]);
#pragma unroll
                for (int mt = 0; mt < 2; ++mt) {
                    asm volatile(
                        "mma.sync.aligned.m16n8k8.row.col.f32.tf32.tf32.f32 "
                        "{%0,%1,%2,%3}, {%4,%5,%6,%7}, {%8,%9}, {%0,%1,%2,%3};"
                        : "+f"(c[mt][nt][0]), "+f"(c[mt][nt][1]),
                          "+f"(c[mt][nt][2]), "+f"(c[mt][nt][3])
                        : "r"(Af[mt][0]), "r"(Af[mt][1]),
                          "r"(Af[mt][2]), "r"(Af[mt][3]),
                          "r"(b0), "r"(b1));
                }
            }
        }

        // ---- build next tile's p directly into buf^1 -------------------
        // Safe: p_s[buf^1]'s last readers (mma of tile it-1) all finished
        // before the previous tail barrier; next readers wait on head(it+1).
        if (more) build_p(buf ^ 1, (it + 1) * BN2);

        __syncthreads();   // tail: all reads of buf done before next writes
    }

    // ---- epilogue: normalize by 1/l, ELU, store -----------------------
#pragma unroll
    for (int mt = 0; mt < 2; ++mt) {
        int row0 = rowbase + mrow + mt * 16 + gr;
        int row1 = row0 + 8;
        float il0 = g_rc[row0].w;
        float il1 = g_rc[row1].w;
#pragma unroll
        for (int nt = 0; nt < 4; ++nt) {
            int col = colbase + ncolL + nt * 8 + tg * 2;
            float v0 = c[mt][nt][0] * il0, v1 = c[mt][nt][1] * il0;
            float v2 = c[mt][nt][2] * il1, v3 = c[mt][nt][3] * il1;
            v0 = (v0 > 0.f) ? v0 : (__expf(v0) - 1.f);
            v1 = (v1 > 0.f) ? v1 : (__expf(v1) - 1.f);
            v2 = (v2 > 0.f) ? v2 : (__expf(v2) - 1.f);
            v3 = (v3 > 0.f) ? v3 : (__expf(v3) - 1.f);
            *(float2*)&out[(size_t)row0 * F_OUT + col] = make_float2(v0, v1);
            *(float2*)&out[(size_t)row1 * F_OUT + col] = make_float2(v2, v3);
        }
    }
}

// ===========================================================================
// launch
// ===========================================================================
extern "C" void kernel_launch(void* const* d_in, const int* in_sizes, int n_in,
                              void* d_out, int out_size)
{
    const float* x   = (const float*)d_in[0];   // [8192, 512]
    const int*   adj = (const int*)  d_in[1];   // [8192, 8192]
    const float* W   = (const float*)d_in[2];   // [512, 256]
    const float* a   = (const float*)d_in[3];   // [512, 1]
    float* out = (float*)d_out;                 // [8192, 256]

    cudaFuncSetAttribute(gat_mma_kernel,
                         cudaFuncAttributeMaxDynamicSharedMemorySize, SMEM_BYTES);

    gemm1_kernel<<<dim3(NN / 64, F_OUT / 64), 256>>>(x, W);
    f12_kernel<<<NN / 8, 256>>>(a);
    rowstats_kernel<<<NN / 8, 256>>>(adj);
    gat_mma_kernel<<<dim3(NN / BM2, F_OUT / NC2), 256, SMEM_BYTES>>>(out);
}

// round 16
// speedup vs baseline: 1.0993x; 1.0993x over previous
#include <cuda_runtime.h>
#include <cuda_fp16.h>
#include <cstdint>

// Problem constants
#define NN    8192
#define F_IN  512
#define F_OUT 256
#define ALPHA 0.2f
#define NEG_INF (-9e15f)
#define FLT_MAXN 3.402823466e38f

// -------- scratch (device globals: no allocations allowed) ----------------
__device__ float   g_h  [NN * F_OUT];  // h = x @ W (fp32, for f1/f2)
// h^T tf32, TILED: [j-tile (32 rows)][n 0..255][j_local 0..31] — each j-tile
// is a contiguous 32 KB block, so gat's cp.async reads are fully sequential.
__device__ float   g_htT[NN * F_OUT];
__device__ float   g_f1[NN];
__device__ float   g_f2[NN];
__device__ __align__(16) float2 g_e2[NN];   // (exp(f2_j), exp(0.2*f2_j))
__device__ float4  g_rc[NN];           // per-row (A, C, Bthr, 1/l)
__device__ uint8_t g_bits[NN * (NN / 8)];  // packed adj>0 bits (8 MB)

__device__ __forceinline__ float to_tf32(float x) {
    uint32_t r;
    asm("cvt.rna.tf32.f32 %0, %1;" : "=r"(r) : "f"(x));
    return __uint_as_float(r);
}

__device__ __forceinline__ uint32_t smem_u32(const void* p) {
    uint32_t a;
    asm("{ .reg .u64 t; cvta.to.shared.u64 t, %1; cvt.u32.u64 %0, t; }"
        : "=r"(a) : "l"(p));
    return a;
}

__device__ __forceinline__ void ldsm4(uint32_t& r0, uint32_t& r1,
                                      uint32_t& r2, uint32_t& r3, uint32_t addr) {
    asm volatile("ldmatrix.sync.aligned.m8n8.x4.shared.b16 {%0,%1,%2,%3}, [%4];"
                 : "=r"(r0), "=r"(r1), "=r"(r2), "=r"(r3) : "r"(addr));
}

// ===========================================================================
// Kernel 1: h = x @ W; writes fp32 h (row major) + tf32 h^T (tiled layout)
// ===========================================================================
__global__ __launch_bounds__(256) void gemm1_kernel(
    const float* __restrict__ X, const float* __restrict__ W)
{
    __shared__ float Xs[16][64];
    __shared__ float Ws[16][64];
    __shared__ float tr[64][68];    // transpose buffer [col][row]

    const int t   = threadIdx.x;
    const int tx  = t & 15;
    const int ty  = t >> 4;
    const int row0 = blockIdx.x * 64;
    const int col0 = blockIdx.y * 64;

    float acc[4][4];
#pragma unroll
    for (int i = 0; i < 4; ++i)
#pragma unroll
        for (int j = 0; j < 4; ++j) acc[i][j] = 0.f;

    for (int k0 = 0; k0 < F_IN; k0 += 16) {
        {
            int r  = t >> 2;
            int kq = (t & 3) * 4;
            float4 v = *(const float4*)&X[(size_t)(row0 + r) * F_IN + k0 + kq];
            Xs[kq + 0][r] = v.x;
            Xs[kq + 1][r] = v.y;
            Xs[kq + 2][r] = v.z;
            Xs[kq + 3][r] = v.w;
        }
        {
            int kr = t >> 4;
            int cq = (t & 15) * 4;
            *(float4*)&Ws[kr][cq] =
                *(const float4*)&W[(size_t)(k0 + kr) * F_OUT + col0 + cq];
        }
        __syncthreads();

#pragma unroll
        for (int kk = 0; kk < 16; ++kk) {
            float a4[4], b4[4];
            *(float4*)a4 = *(const float4*)&Xs[kk][ty * 4];
            *(float4*)b4 = *(const float4*)&Ws[kk][tx * 4];
#pragma unroll
            for (int i = 0; i < 4; ++i)
#pragma unroll
                for (int j = 0; j < 4; ++j)
                    acc[i][j] = fmaf(a4[i], b4[j], acc[i][j]);
        }
        __syncthreads();
    }

    // fp32 h (row major) + tf32 transpose staging
#pragma unroll
    for (int i = 0; i < 4; ++i) {
        size_t off = (size_t)(row0 + ty * 4 + i) * F_OUT + col0 + tx * 4;
        *(float4*)&g_h[off] = make_float4(acc[i][0], acc[i][1], acc[i][2], acc[i][3]);
#pragma unroll
        for (int j = 0; j < 4; ++j)
            tr[tx * 4 + j][ty * 4 + i] = to_tf32(acc[i][j]);
    }
    __syncthreads();

    // write tiled-transposed h^T: block covers j-tiles (row0/32) and (row0/32)+1
    {
        int col = t >> 2;            // local col 0..63
        int q   = t & 3;
#pragma unroll
        for (int ht = 0; ht < 2; ++ht) {
            int jt = (row0 >> 5) + ht;
            float* dst = &g_htT[(size_t)jt * (F_OUT * 32) + (col0 + col) * 32];
#pragma unroll
            for (int r = 0; r < 2; ++r) {
                int j4 = (q * 2 + r) * 4;      // 0..28
                *(float4*)&dst[j4] = *(const float4*)&tr[col][ht * 32 + j4];
            }
        }
    }
}

// ===========================================================================
// Kernel 2: f1 / f2 row dot products + e2 table
// ===========================================================================
__global__ __launch_bounds__(256) void f12_kernel(const float* __restrict__ a)
{
    const int warp = threadIdx.x >> 5;
    const int lane = threadIdx.x & 31;
    const int row  = blockIdx.x * 8 + warp;
    if (row >= NN) return;

    const float* hr = &g_h[(size_t)row * F_OUT];
    float s1 = 0.f, s2 = 0.f;
#pragma unroll
    for (int q = 0; q < 8; ++q) {
        int f = lane + q * 32;
        float v = hr[f];
        s1 = fmaf(v, a[f], s1);
        s2 = fmaf(v, a[F_OUT + f], s2);
    }
#pragma unroll
    for (int off = 16; off > 0; off >>= 1) {
        s1 += __shfl_xor_sync(0xffffffffu, s1, off);
        s2 += __shfl_xor_sync(0xffffffffu, s2, off);
    }
    if (lane == 0) {
        g_f1[row] = s1;
        g_f2[row] = s2;
        g_e2[row] = make_float2(__expf(s2), __expf(ALPHA * s2));
    }
}

// ===========================================================================
// Kernel 3: rowstats — streams adj + f2. Online (m, l) stats, emits
// rc = (A, C, Bthr, 1/l) and the packed adjacency bits.
// ===========================================================================
__global__ __launch_bounds__(256) void rowstats_kernel(const int* __restrict__ adj)
{
    const int warp = threadIdx.x >> 5;
    const int lane = threadIdx.x & 31;
    const int row  = blockIdx.x * 8 + warp;

    const int* arow = adj + (size_t)row * NN;
    uint8_t* brow   = g_bits + (size_t)row * (NN / 8);
    const float f1v = g_f1[row];

    float m = -FLT_MAXN;
    float l = 0.f;

    for (int j0 = lane * 8; j0 < NN; j0 += 256) {
        int4   A0 = *(const int4*)&arow[j0];
        int4   A1 = *(const int4*)&arow[j0 + 4];
        float4 F0 = *(const float4*)&g_f2[j0];
        float4 F1 = *(const float4*)&g_f2[j0 + 4];

        int   av[8] = {A0.x, A0.y, A0.z, A0.w, A1.x, A1.y, A1.z, A1.w};
        float fv[8] = {F0.x, F0.y, F0.z, F0.w, F1.x, F1.y, F1.z, F1.w};
        float sv[8];
        uint32_t bits = 0;
#pragma unroll
        for (int k = 0; k < 8; ++k) {
            float e = f1v + fv[k];
            e = (e > 0.f) ? e : ALPHA * e;
            bool msk = av[k] > 0;
            sv[k] = msk ? e : NEG_INF;
            bits |= (msk ? 1u : 0u) << k;
        }
        brow[j0 >> 3] = (uint8_t)bits;

        float cm = sv[0];
#pragma unroll
        for (int k = 1; k < 8; ++k) cm = fmaxf(cm, sv[k]);
        float mn = fmaxf(m, cm);
        float s = 0.f;
#pragma unroll
        for (int k = 0; k < 8; ++k) s += __expf(sv[k] - mn);
        l = l * __expf(m - mn) + s;
        m = mn;
    }

#pragma unroll
    for (int off = 16; off > 0; off >>= 1) {
        float m2 = __shfl_xor_sync(0xffffffffu, m, off);
        float l2 = __shfl_xor_sync(0xffffffffu, l, off);
        float mn = fmaxf(m, m2);
        l = l * __expf(m - mn) + l2 * __expf(m2 - mn);
        m = mn;
    }
    if (lane == 0) {
        float A = 0.f, C = 0.f, il = 0.f;
        if (l > 0.f) {
            A  = __expf(f1v - m);
            C  = __expf(ALPHA * f1v - m);
            il = 1.f / l;
        }
        g_rc[row] = make_float4(A, C, __expf(-f1v), il);
    }
}

// ===========================================================================
// Kernel 4: att @ h via tf32 mma m16n8k8 — round-12 structure + ldsm for
// BOTH operands. Fragment lane mapping uses the round-7-PROVEN convention:
//   lane bit3 (lp8) -> +8 rows (ldmatrix matrices 1,3)
//   lane bit4 (lc4) -> +4 float-cols (matrices 2,3)
// A frags: a0..a3 = matrices 0..3 directly.
// B frags (from [n][k] smem): matrix order is (n+0,k+0),(n+8,k+0),
//   (n+0,k+4),(n+8,k+4), so b0 = Bf[nt>>1][nt&1], b1 = Bf[nt>>1][(nt&1)+2].
// ===========================================================================
#define BM2    64
#define BN2    32
#define NT     (NN / BN2)           // 256 tiles
#define PS     36                   // p_s row stride (floats)
#define KS     36                   // h_s row stride (floats): 32 k + 4 pad
#define HBUF_F (256 * KS)           // 9216 floats per h buffer
#define PBUF_F (BM2 * PS)           // 2304 floats per p buffer
#define SMEM_BYTES ((2 * HBUF_F + 2 * PBUF_F) * 4)   // 92160 B

__global__ __launch_bounds__(512) void gat_mma_kernel(float* __restrict__ out)
{
    extern __shared__ float smemf[];
    float* h_s = smemf;                  // [2][256 n][KS]  ([n][k])
    float* p_s = smemf + 2 * HBUF_F;     // [2][BM2][PS]    ([m][k])
    const uint32_t h_a = smem_u32(h_s);
    const uint32_t p_a = smem_u32(p_s);

    const int t    = threadIdx.x;
    const int warp = t >> 5;
    const int lane = t & 31;
    const int rowbase = blockIdx.x * BM2;

    // mma mapping: warp (w&1) -> 32-row half, (w>>1) -> 32 cols of 256
    const int mrow = (warp & 1) * 32;
    const int ncol = (warp >> 1) * 32;
    const int gr   = lane >> 2;
    const int tg   = lane & 3;

    // ldmatrix lane offsets — round-7-proven convention
    const int lrow = lane & 7;
    const int lp8  = (lane >> 3) & 1;   // +8 rows (matrices 1,3)
    const int lc4  = (lane >> 4) & 1;   // +4 float-cols (matrices 2,3)
    int aoff[2];
#pragma unroll
    for (int mt = 0; mt < 2; ++mt)
        aoff[mt] = (mrow + mt * 16 + lp8 * 8 + lrow) * PS + lc4 * 4;
    int boff[2];
#pragma unroll
    for (int pp = 0; pp < 2; ++pp)
        boff[pp] = (ncol + pp * 16 + lp8 * 8 + lrow) * KS + lc4 * 4;

    // p-build mapping: thread -> row pr (0..63), 4 j at pj
    const int pr = t >> 3;
    const int pj = (t & 7) * 4;
    const float4 rc = g_rc[rowbase + pr];      // (A, C, Bthr, il)
    const uint8_t* brow = g_bits + (size_t)(rowbase + pr) * (NN / 8);

    float c[2][4][4];                // [m-tile][n-tile][frag]
#pragma unroll
    for (int mt = 0; mt < 2; ++mt)
#pragma unroll
        for (int nt = 0; nt < 4; ++nt)
#pragma unroll
            for (int q = 0; q < 4; ++q) c[mt][nt][q] = 0.f;

    // cp.async h tile (contiguous 32 KB from tiled g_htT)
    auto load_h = [&](int bufIdx, int jt) {
        const float* src = &g_htT[(size_t)jt * (F_OUT * 32)];
#pragma unroll
        for (int q = 0; q < 4; ++q) {
            int fi = q * 512 + t;            // float4 idx 0..2047
            int n  = fi >> 3;                // 8 float4 per n row
            int j4 = (fi & 7) * 4;
            uint32_t dst = h_a + (uint32_t)(bufIdx * HBUF_F + n * KS + j4) * 4;
            asm volatile("cp.async.cg.shared.global [%0], [%1], 16;\n"
                         :: "r"(dst), "l"(src + fi * 4));
        }
        asm volatile("cp.async.commit_group;\n" ::: "memory");
    };

    // ---------------- prologue: tile 0 ---------------------------------
    float4 phv;
    {
        uint32_t w = brow[0] | ((uint32_t)brow[1] << 8)
                   | ((uint32_t)brow[2] << 16) | ((uint32_t)brow[3] << 24);
        float4 E0 = *(const float4*)&g_e2[pj];
        float4 E1 = *(const float4*)&g_e2[pj + 2];
        float bv[4] = {E0.x, E0.z, E1.x, E1.z};
        float dv[4] = {E0.y, E0.w, E1.y, E1.w};
        float pv[4];
#pragma unroll
        for (int k = 0; k < 4; ++k) {
            bool msk = (w >> (pj + k)) & 1u;
            bool cond = bv[k] > rc.z;
            float p = (cond ? bv[k] : dv[k]) * (cond ? rc.x : rc.y);
            pv[k] = to_tf32(msk ? p : 0.f);
        }
        phv = make_float4(pv[0], pv[1], pv[2], pv[3]);
    }
    load_h(0, 0);

    // ---------------- main loop ----------------------------------------
    for (int it = 0; it < NT; ++it) {
        const int buf = it & 1;
        const bool more = (it + 1 < NT);
        uint32_t nW = 0;
        float4 nE0, nE1;

        if (more) {
            int jn = (it + 1) * BN2;
            load_h(buf ^ 1, it + 1);
            // EARLY prefetch of next p inputs — latency overlaps the mma
            nW  = *(const uint32_t*)&brow[jn >> 3];
            nE0 = *(const float4*)&g_e2[jn + pj];
            nE1 = *(const float4*)&g_e2[jn + pj + 2];
        }

        *(float4*)&p_s[buf * PBUF_F + pr * PS + pj] = phv;

        if (more) asm volatile("cp.async.wait_group 1;\n" ::: "memory");
        else      asm volatile("cp.async.wait_group 0;\n" ::: "memory");
        __syncthreads();   // head: h(it) + p(it) visible

        // ---- tensor-core GEMM on this tile -----------------------------
        const uint32_t pbase = p_a + (uint32_t)(buf * PBUF_F) * 4;
        const uint32_t hbase = h_a + (uint32_t)(buf * HBUF_F) * 4;
#pragma unroll
        for (int ks = 0; ks < 4; ++ks) {
            int kb = ks * 8;
            uint32_t Af[2][4];
            ldsm4(Af[0][0], Af[0][1], Af[0][2], Af[0][3],
                  pbase + (uint32_t)(aoff[0] + kb) * 4);
            ldsm4(Af[1][0], Af[1][1], Af[1][2], Af[1][3],
                  pbase + (uint32_t)(aoff[1] + kb) * 4);
            uint32_t Bf[2][4];
            ldsm4(Bf[0][0], Bf[0][1], Bf[0][2], Bf[0][3],
                  hbase + (uint32_t)(boff[0] + kb) * 4);
            ldsm4(Bf[1][0], Bf[1][1], Bf[1][2], Bf[1][3],
                  hbase + (uint32_t)(boff[1] + kb) * 4);
#pragma unroll
            for (int nt = 0; nt < 4; ++nt) {
                uint32_t b0 = Bf[nt >> 1][nt & 1];        // k 0-3  at n-block
                uint32_t b1 = Bf[nt >> 1][(nt & 1) + 2];  // k 4-7  at n-block
#pragma unroll
                for (int mt = 0; mt < 2; ++mt) {
                    asm volatile(
                        "mma.sync.aligned.m16n8k8.row.col.f32.tf32.tf32.f32 "
                        "{%0,%1,%2,%3}, {%4,%5,%6,%7}, {%8,%9}, {%0,%1,%2,%3};"
                        : "+f"(c[mt][nt][0]), "+f"(c[mt][nt][1]),
                          "+f"(c[mt][nt][2]), "+f"(c[mt][nt][3])
                        : "r"(Af[mt][0]), "r"(Af[mt][1]),
                          "r"(Af[mt][2]), "r"(Af[mt][3]),
                          "r"(b0), "r"(b1));
                }
            }
        }

        // ---- build next tile's p from the early-prefetched registers ---
        if (more) {
            float bv[4] = {nE0.x, nE0.z, nE1.x, nE1.z};
            float dv[4] = {nE0.y, nE0.w, nE1.y, nE1.w};
            float pv[4];
#pragma unroll
            for (int k = 0; k < 4; ++k) {
                bool msk = (nW >> (pj + k)) & 1u;
                bool cond = bv[k] > rc.z;
                float p = (cond ? bv[k] : dv[k]) * (cond ? rc.x : rc.y);
                pv[k] = to_tf32(msk ? p : 0.f);
            }
            phv = make_float4(pv[0], pv[1], pv[2], pv[3]);
        }

        // tail barrier: all reads of buf done before next-iteration writes.
        __syncthreads();
    }

    // ---- epilogue: normalize by 1/l, ELU, store -----------------------
#pragma unroll
    for (int mt = 0; mt < 2; ++mt) {
        int row0 = rowbase + mrow + mt * 16 + gr;
        int row1 = row0 + 8;
        float il0 = g_rc[row0].w;
        float il1 = g_rc[row1].w;
#pragma unroll
        for (int nt = 0; nt < 4; ++nt) {
            int col = ncol + nt * 8 + tg * 2;
            float v0 = c[mt][nt][0] * il0, v1 = c[mt][nt][1] * il0;
            float v2 = c[mt][nt][2] * il1, v3 = c[mt][nt][3] * il1;
            v0 = (v0 > 0.f) ? v0 : (__expf(v0) - 1.f);
            v1 = (v1 > 0.f) ? v1 : (__expf(v1) - 1.f);
            v2 = (v2 > 0.f) ? v2 : (__expf(v2) - 1.f);
            v3 = (v3 > 0.f) ? v3 : (__expf(v3) - 1.f);
            *(float2*)&out[(size_t)row0 * F_OUT + col] = make_float2(v0, v1);
            *(float2*)&out[(size_t)row1 * F_OUT + col] = make_float2(v2, v3);
        }
    }
}

// ===========================================================================
// launch
// ===========================================================================
extern "C" void kernel_launch(void* const* d_in, const int* in_sizes, int n_in,
                              void* d_out, int out_size)
{
    const float* x   = (const float*)d_in[0];   // [8192, 512]
    const int*   adj = (const int*)  d_in[1];   // [8192, 8192]
    const float* W   = (const float*)d_in[2];   // [512, 256]
    const float* a   = (const float*)d_in[3];   // [512, 1]
    float* out = (float*)d_out;                 // [8192, 256]

    cudaFuncSetAttribute(gat_mma_kernel,
                         cudaFuncAttributeMaxDynamicSharedMemorySize, SMEM_BYTES);

    gemm1_kernel<<<dim3(NN / 64, F_OUT / 64), 256>>>(x, W);
    f12_kernel<<<NN / 8, 256>>>(a);
    rowstats_kernel<<<NN / 8, 256>>>(adj);
    gat_mma_kernel<<<NN / BM2, 512, SMEM_BYTES>>>(out);
}

// round 17
// speedup vs baseline: 1.1830x; 1.0762x over previous
#include <cuda_runtime.h>
#include <cuda_fp16.h>
#include <cstdint>

// Problem constants
#define NN    8192
#define F_IN  512
#define F_OUT 256
#define ALPHA 0.2f
#define NEG_INF (-9e15f)
#define FLT_MAXN 3.402823466e38f

// -------- scratch (device globals: no allocations allowed) ----------------
__device__ float   g_h  [NN * F_OUT];  // h = x @ W (fp32, for f1/f2)
// h^T tf32, TILED: [j-tile (32 rows)][n 0..255][j_local 0..31] — each j-tile
// is a contiguous 32 KB block, so gat's cp.async reads are fully sequential.
__device__ float   g_htT[NN * F_OUT];
__device__ float   g_f1[NN];
__device__ float   g_f2[NN];
__device__ __align__(16) float2 g_e2[NN];   // (exp(f2_j), exp(0.2*f2_j))
__device__ float4  g_rc[NN];           // per-row (A, C, Bthr, 1/l)
__device__ uint8_t g_bits[NN * (NN / 8)];  // packed adj>0 bits (8 MB)

__device__ __forceinline__ float to_tf32(float x) {
    uint32_t r;
    asm("cvt.rna.tf32.f32 %0, %1;" : "=r"(r) : "f"(x));
    return __uint_as_float(r);
}

__device__ __forceinline__ uint32_t smem_u32(const void* p) {
    uint32_t a;
    asm("{ .reg .u64 t; cvta.to.shared.u64 t, %1; cvt.u32.u64 %0, t; }"
        : "=r"(a) : "l"(p));
    return a;
}

__device__ __forceinline__ void ldsm4(uint32_t& r0, uint32_t& r1,
                                      uint32_t& r2, uint32_t& r3, uint32_t addr) {
    asm volatile("ldmatrix.sync.aligned.m8n8.x4.shared.b16 {%0,%1,%2,%3}, [%4];"
                 : "=r"(r0), "=r"(r1), "=r"(r2), "=r"(r3) : "r"(addr));
}

// ===========================================================================
// Kernel 1: h = x @ W; writes fp32 h (row major) + tf32 h^T (tiled layout)
// ===========================================================================
__global__ __launch_bounds__(256) void gemm1_kernel(
    const float* __restrict__ X, const float* __restrict__ W)
{
    __shared__ float Xs[16][64];
    __shared__ float Ws[16][64];
    __shared__ float tr[64][68];    // transpose buffer [col][row]

    const int t   = threadIdx.x;
    const int tx  = t & 15;
    const int ty  = t >> 4;
    const int row0 = blockIdx.x * 64;
    const int col0 = blockIdx.y * 64;

    float acc[4][4];
#pragma unroll
    for (int i = 0; i < 4; ++i)
#pragma unroll
        for (int j = 0; j < 4; ++j) acc[i][j] = 0.f;

    for (int k0 = 0; k0 < F_IN; k0 += 16) {
        {
            int r  = t >> 2;
            int kq = (t & 3) * 4;
            float4 v = *(const float4*)&X[(size_t)(row0 + r) * F_IN + k0 + kq];
            Xs[kq + 0][r] = v.x;
            Xs[kq + 1][r] = v.y;
            Xs[kq + 2][r] = v.z;
            Xs[kq + 3][r] = v.w;
        }
        {
            int kr = t >> 4;
            int cq = (t & 15) * 4;
            *(float4*)&Ws[kr][cq] =
                *(const float4*)&W[(size_t)(k0 + kr) * F_OUT + col0 + cq];
        }
        __syncthreads();

#pragma unroll
        for (int kk = 0; kk < 16; ++kk) {
            float a4[4], b4[4];
            *(float4*)a4 = *(const float4*)&Xs[kk][ty * 4];
            *(float4*)b4 = *(const float4*)&Ws[kk][tx * 4];
#pragma unroll
            for (int i = 0; i < 4; ++i)
#pragma unroll
                for (int j = 0; j < 4; ++j)
                    acc[i][j] = fmaf(a4[i], b4[j], acc[i][j]);
        }
        __syncthreads();
    }

    // fp32 h (row major) + tf32 transpose staging
#pragma unroll
    for (int i = 0; i < 4; ++i) {
        size_t off = (size_t)(row0 + ty * 4 + i) * F_OUT + col0 + tx * 4;
        *(float4*)&g_h[off] = make_float4(acc[i][0], acc[i][1], acc[i][2], acc[i][3]);
#pragma unroll
        for (int j = 0; j < 4; ++j)
            tr[tx * 4 + j][ty * 4 + i] = to_tf32(acc[i][j]);
    }
    __syncthreads();

    // write tiled-transposed h^T: block covers j-tiles (row0/32) and (row0/32)+1
    {
        int col = t >> 2;            // local col 0..63
        int q   = t & 3;
#pragma unroll
        for (int ht = 0; ht < 2; ++ht) {
            int jt = (row0 >> 5) + ht;
            float* dst = &g_htT[(size_t)jt * (F_OUT * 32) + (col0 + col) * 32];
#pragma unroll
            for (int r = 0; r < 2; ++r) {
                int j4 = (q * 2 + r) * 4;      // 0..28
                *(float4*)&dst[j4] = *(const float4*)&tr[col][ht * 32 + j4];
            }
        }
    }
}

// ===========================================================================
// Kernel 2: f1 / f2 row dot products + e2 table
// ===========================================================================
__global__ __launch_bounds__(256) void f12_kernel(const float* __restrict__ a)
{
    const int warp = threadIdx.x >> 5;
    const int lane = threadIdx.x & 31;
    const int row  = blockIdx.x * 8 + warp;
    if (row >= NN) return;

    const float* hr = &g_h[(size_t)row * F_OUT];
    float s1 = 0.f, s2 = 0.f;
#pragma unroll
    for (int q = 0; q < 8; ++q) {
        int f = lane + q * 32;
        float v = hr[f];
        s1 = fmaf(v, a[f], s1);
        s2 = fmaf(v, a[F_OUT + f], s2);
    }
#pragma unroll
    for (int off = 16; off > 0; off >>= 1) {
        s1 += __shfl_xor_sync(0xffffffffu, s1, off);
        s2 += __shfl_xor_sync(0xffffffffu, s2, off);
    }
    if (lane == 0) {
        g_f1[row] = s1;
        g_f2[row] = s2;
        g_e2[row] = make_float2(__expf(s2), __expf(ALPHA * s2));
    }
}

// ===========================================================================
// Kernel 3: rowstats — streams adj + f2. Online (m, l) stats, emits
// rc = (A, C, Bthr, 1/l) and the packed adjacency bits.
// ===========================================================================
__global__ __launch_bounds__(256) void rowstats_kernel(const int* __restrict__ adj)
{
    const int warp = threadIdx.x >> 5;
    const int lane = threadIdx.x & 31;
    const int row  = blockIdx.x * 8 + warp;

    const int* arow = adj + (size_t)row * NN;
    uint8_t* brow   = g_bits + (size_t)row * (NN / 8);
    const float f1v = g_f1[row];

    float m = -FLT_MAXN;
    float l = 0.f;

    for (int j0 = lane * 8; j0 < NN; j0 += 256) {
        int4   A0 = *(const int4*)&arow[j0];
        int4   A1 = *(const int4*)&arow[j0 + 4];
        float4 F0 = *(const float4*)&g_f2[j0];
        float4 F1 = *(const float4*)&g_f2[j0 + 4];

        int   av[8] = {A0.x, A0.y, A0.z, A0.w, A1.x, A1.y, A1.z, A1.w};
        float fv[8] = {F0.x, F0.y, F0.z, F0.w, F1.x, F1.y, F1.z, F1.w};
        float sv[8];
        uint32_t bits = 0;
#pragma unroll
        for (int k = 0; k < 8; ++k) {
            float e = f1v + fv[k];
            e = (e > 0.f) ? e : ALPHA * e;
            bool msk = av[k] > 0;
            sv[k] = msk ? e : NEG_INF;
            bits |= (msk ? 1u : 0u) << k;
        }
        brow[j0 >> 3] = (uint8_t)bits;

        float cm = sv[0];
#pragma unroll
        for (int k = 1; k < 8; ++k) cm = fmaxf(cm, sv[k]);
        float mn = fmaxf(m, cm);
        float s = 0.f;
#pragma unroll
        for (int k = 0; k < 8; ++k) s += __expf(sv[k] - mn);
        l = l * __expf(m - mn) + s;
        m = mn;
    }

#pragma unroll
    for (int off = 16; off > 0; off >>= 1) {
        float m2 = __shfl_xor_sync(0xffffffffu, m, off);
        float l2 = __shfl_xor_sync(0xffffffffu, l, off);
        float mn = fmaxf(m, m2);
        l = l * __expf(m - mn) + l2 * __expf(m2 - mn);
        m = mn;
    }
    if (lane == 0) {
        float A = 0.f, C = 0.f, il = 0.f;
        if (l > 0.f) {
            A  = __expf(f1v - m);
            C  = __expf(ALPHA * f1v - m);
            il = 1.f / l;
        }
        g_rc[row] = make_float4(A, C, __expf(-f1v), il);
    }
}

// ===========================================================================
// Kernel 4: att @ h via tf32 mma m16n8k8 — 4-STAGE pipeline, ONE barrier
// per tile (prefetch distance 2; stage (it+2)%4's last readers ran at
// iteration it-2, separated from this iteration's writes by barrier(it-1)).
// cp groups in flight <= 2 (empty commit groups keep the count invariant).
// ldsm for both operands (round-16-proven lane mapping).
// ===========================================================================
#define BM2    64
#define BN2    32
#define NT     (NN / BN2)           // 256 tiles
#define NSTG   4
#define PS     36                   // p_s row stride (floats)
#define KS     36                   // h_s row stride (floats): 32 k + 4 pad
#define HBUF_F (256 * KS)           // 9216 floats per h stage
#define PBUF_F (BM2 * PS)           // 2304 floats per p stage
#define SMEM_BYTES ((NSTG * HBUF_F + NSTG * PBUF_F) * 4)   // 184320 B

__global__ __launch_bounds__(512) void gat_mma_kernel(float* __restrict__ out)
{
    extern __shared__ float smemf[];
    float* h_s = smemf;                       // [NSTG][256 n][KS]  ([n][k])
    float* p_s = smemf + NSTG * HBUF_F;       // [NSTG][BM2][PS]    ([m][k])
    const uint32_t h_a = smem_u32(h_s);
    const uint32_t p_a = smem_u32(p_s);

    const int t    = threadIdx.x;
    const int warp = t >> 5;
    const int lane = t & 31;
    const int rowbase = blockIdx.x * BM2;

    // mma mapping: warp (w&1) -> 32-row half, (w>>1) -> 32 cols of 256
    const int mrow = (warp & 1) * 32;
    const int ncol = (warp >> 1) * 32;
    const int gr   = lane >> 2;
    const int tg   = lane & 3;

    // ldmatrix lane offsets — proven convention (r7/r16)
    const int lrow = lane & 7;
    const int lp8  = (lane >> 3) & 1;   // +8 rows (matrices 1,3)
    const int lc4  = (lane >> 4) & 1;   // +4 float-cols (matrices 2,3)
    int aoff[2];
#pragma unroll
    for (int mt = 0; mt < 2; ++mt)
        aoff[mt] = (mrow + mt * 16 + lp8 * 8 + lrow) * PS + lc4 * 4;
    int boff[2];
#pragma unroll
    for (int pp = 0; pp < 2; ++pp)
        boff[pp] = (ncol + pp * 16 + lp8 * 8 + lrow) * KS + lc4 * 4;

    // p-build mapping: thread -> row pr (0..63), 4 j at pj
    const int pr = t >> 3;
    const int pj = (t & 7) * 4;
    const float4 rc = g_rc[rowbase + pr];      // (A, C, Bthr, il)
    const uint8_t* brow = g_bits + (size_t)(rowbase + pr) * (NN / 8);

    float c[2][4][4];                // [m-tile][n-tile][frag]
#pragma unroll
    for (int mt = 0; mt < 2; ++mt)
#pragma unroll
        for (int nt = 0; nt < 4; ++nt)
#pragma unroll
            for (int q = 0; q < 4; ++q) c[mt][nt][q] = 0.f;

    // build p for tile jt into stage st (loads + compute + store)
    auto build_p = [&](int st, int jt) {
        int jn = jt * BN2;
        uint32_t w = *(const uint32_t*)&brow[jn >> 3];
        float4 E0 = *(const float4*)&g_e2[jn + pj];
        float4 E1 = *(const float4*)&g_e2[jn + pj + 2];
        float bv[4] = {E0.x, E0.z, E1.x, E1.z};
        float dv[4] = {E0.y, E0.w, E1.y, E1.w};
        float pv[4];
#pragma unroll
        for (int k = 0; k < 4; ++k) {
            bool msk = (w >> (pj + k)) & 1u;
            bool cond = bv[k] > rc.z;
            float p = (cond ? bv[k] : dv[k]) * (cond ? rc.x : rc.y);
            pv[k] = to_tf32(msk ? p : 0.f);
        }
        *(float4*)&p_s[st * PBUF_F + pr * PS + pj] =
            make_float4(pv[0], pv[1], pv[2], pv[3]);
    };

    // cp.async h tile jt into stage st (contiguous 32 KB from tiled g_htT)
    auto load_h = [&](int st, int jt) {
        const float* src = &g_htT[(size_t)jt * (F_OUT * 32)];
#pragma unroll
        for (int q = 0; q < 4; ++q) {
            int fi = q * 512 + t;            // float4 idx 0..2047
            int n  = fi >> 3;                // 8 float4 per n row
            int j4 = (fi & 7) * 4;
            uint32_t dst = h_a + (uint32_t)(st * HBUF_F + n * KS + j4) * 4;
            asm volatile("cp.async.cg.shared.global [%0], [%1], 16;\n"
                         :: "r"(dst), "l"(src + fi * 4));
        }
    };

    // ---------------- prologue: tiles 0 and 1 ---------------------------
    build_p(0, 0);
    build_p(1, 1);
    load_h(0, 0);
    asm volatile("cp.async.commit_group;\n" ::: "memory");
    load_h(1, 1);
    asm volatile("cp.async.commit_group;\n" ::: "memory");

    // ---------------- main loop (ONE barrier per tile) ------------------
    for (int it = 0; it < NT; ++it) {
        const int stage = it & (NSTG - 1);
        const bool more2 = (it + 2 < NT);
        uint32_t nW = 0;
        float4 nE0, nE1;

        // prefetch for tile it+2: h via cp.async, p inputs into registers
        if (more2) {
            int jn2 = (it + 2) * BN2;
            load_h((it + 2) & (NSTG - 1), it + 2);
            nW  = *(const uint32_t*)&brow[jn2 >> 3];
            nE0 = *(const float4*)&g_e2[jn2 + pj];
            nE1 = *(const float4*)&g_e2[jn2 + pj + 2];
        }
        asm volatile("cp.async.commit_group;\n" ::: "memory");  // keep count
        asm volatile("cp.async.wait_group 2;\n" ::: "memory");  // tile it done
        __syncthreads();   // the ONLY barrier per tile

        // ---- tensor-core GEMM on this tile -----------------------------
        const uint32_t pbase = p_a + (uint32_t)(stage * PBUF_F) * 4;
        const uint32_t hbase = h_a + (uint32_t)(stage * HBUF_F) * 4;
#pragma unroll
        for (int ks = 0; ks < 4; ++ks) {
            int kb = ks * 8;
            uint32_t Af[2][4];
            ldsm4(Af[0][0], Af[0][1], Af[0][2], Af[0][3],
                  pbase + (uint32_t)(aoff[0] + kb) * 4);
            ldsm4(Af[1][0], Af[1][1], Af[1][2], Af[1][3],
                  pbase + (uint32_t)(aoff[1] + kb) * 4);
            uint32_t Bf[2][4];
            ldsm4(Bf[0][0], Bf[0][1], Bf[0][2], Bf[0][3],
                  hbase + (uint32_t)(boff[0] + kb) * 4);
            ldsm4(Bf[1][0], Bf[1][1], Bf[1][2], Bf[1][3],
                  hbase + (uint32_t)(boff[1] + kb) * 4);
#pragma unroll
            for (int nt = 0; nt < 4; ++nt) {
                uint32_t b0 = Bf[nt >> 1][nt & 1];        // k 0-3
                uint32_t b1 = Bf[nt >> 1][(nt & 1) + 2];  // k 4-7
#pragma unroll
                for (int mt = 0; mt < 2; ++mt) {
                    asm volatile(
                        "mma.sync.aligned.m16n8k8.row.col.f32.tf32.tf32.f32 "
                        "{%0,%1,%2,%3}, {%4,%5,%6,%7}, {%8,%9}, {%0,%1,%2,%3};"
                        : "+f"(c[mt][nt][0]), "+f"(c[mt][nt][1]),
                          "+f"(c[mt][nt][2]), "+f"(c[mt][nt][3])
                        : "r"(Af[mt][0]), "r"(Af[mt][1]),
                          "r"(Af[mt][2]), "r"(Af[mt][3]),
                        "r"(b0), "r"(b1));
                }
            }
        }

        // ---- compute + store p(it+2) from prefetched registers ---------
        // Writes stage (it+2)%4 AFTER barrier(it); its last readers ran at
        // iteration it-2, before barrier(it-1) <= barrier(it). Race-free.
        if (more2) {
            float bv[4] = {nE0.x, nE0.z, nE1.x, nE1.z};
            float dv[4] = {nE0.y, nE0.w, nE1.y, nE1.w};
            float pv[4];
#pragma unroll
            for (int k = 0; k < 4; ++k) {
                bool msk = (nW >> (pj + k)) & 1u;
                bool cond = bv[k] > rc.z;
                float p = (cond ? bv[k] : dv[k]) * (cond ? rc.x : rc.y);
                pv[k] = to_tf32(msk ? p : 0.f);
            }
            *(float4*)&p_s[((it + 2) & (NSTG - 1)) * PBUF_F + pr * PS + pj] =
                make_float4(pv[0], pv[1], pv[2], pv[3]);
        }
    }

    // ---- epilogue: normalize by 1/l, ELU, store -----------------------
#pragma unroll
    for (int mt = 0; mt < 2; ++mt) {
        int row0 = rowbase + mrow + mt * 16 + gr;
        int row1 = row0 + 8;
        float il0 = g_rc[row0].w;
        float il1 = g_rc[row1].w;
#pragma unroll
        for (int nt = 0; nt < 4; ++nt) {
            int col = ncol + nt * 8 + tg * 2;
            float v0 = c[mt][nt][0] * il0, v1 = c[mt][nt][1] * il0;
            float v2 = c[mt][nt][2] * il1, v3 = c[mt][nt][3] * il1;
            v0 = (v0 > 0.f) ? v0 : (__expf(v0) - 1.f);
            v1 = (v1 > 0.f) ? v1 : (__expf(v1) - 1.f);
            v2 = (v2 > 0.f) ? v2 : (__expf(v2) - 1.f);
            v3 = (v3 > 0.f) ? v3 : (__expf(v3) - 1.f);
            *(float2*)&out[(size_t)row0 * F_OUT + col] = make_float2(v0, v1);
            *(float2*)&out[(size_t)row1 * F_OUT + col] = make_float2(v2, v3);
        }
    }
}

// ===========================================================================
// launch
// ===========================================================================
extern "C" void kernel_launch(void* const* d_in, const int* in_sizes, int n_in,
                              void* d_out, int out_size)
{
    const float* x   = (const float*)d_in[0];   // [8192, 512]
    const int*   adj = (const int*)  d_in[1];   // [8192, 8192]
    const float* W   = (const float*)d_in[2];   // [512, 256]
    const float* a   = (const float*)d_in[3];   // [512, 1]
    float* out = (float*)d_out;                 // [8192, 256]

    cudaFuncSetAttribute(gat_mma_kernel,
                         cudaFuncAttributeMaxDynamicSharedMemorySize, SMEM_BYTES);

    gemm1_kernel<<<dim3(NN / 64, F_OUT / 64), 256>>>(x, W);
    f12_kernel<<<NN / 8, 256>>>(a);
    rowstats_kernel<<<NN / 8, 256>>>(adj);
    gat_mma_kernel<<<NN / BM2, 512, SMEM_BYTES>>>(out);
}